// round 11
// baseline (speedup 1.0000x reference)
#include <cuda_runtime.h>
#include <cuda_fp16.h>
#include <mma.h>

using namespace nvcuda;

#define NMAX  100000
#define NPAD  100352        // 1024 * 98, multiple of 128
#define NBLK  98            // NPAD / 1024
#define EMAX  1600000
#define HID   64

#define LB_AGG (1ULL << 32)
#define LB_PRE (2ULL << 32)

// ---------------- scratch (device globals; no allocation) ----------------
__device__ __align__(16) float  d_dis[NPAD];          // deg_inv_sqrt
__device__ __align__(16) __half d_gh[NPAD * HID];     // layer-1 h (fp16, raw)
__device__ __align__(16) __half d_gh2[NPAD * HID];    // layer-2 h * dis (fp16, premultiplied)
__device__ __align__(16) float  d_g3[NPAD];           // layer-3 h*dis
__device__ int d_csr[EMAX];                           // src ids grouped by dst
__device__ int d_rank[EMAX];                          // per-edge rank within its dst
__device__ int d_cnt[NPAD];                           // indegree (zero-init; scan re-zeroes)
__device__ int d_rowstart[NPAD + 1];                  // exclusive prefix of cnt
__device__ unsigned long long d_lb[NBLK];             // decoupled-lookback state

// ---------------- preprocessing ----------------
// count + rank: one atomic per edge; rank = this edge's slot within its dst bucket
__global__ void k_count(const int* __restrict__ ei, int E, int N) {
    if (blockIdx.x == 0 && threadIdx.x < NBLK) d_lb[threadIdx.x] = 0;   // reset lookback state
    int e = blockIdx.x * blockDim.x + threadIdx.x;
    if (e < E) {
        unsigned d = (unsigned)ei[E + e];
        if (d < (unsigned)N) d_rank[e] = atomicAdd(&d_cnt[d], 1);
    }
}

// single-pass scan: per-block reduce -> publish -> in-block scan -> lookback -> rowstart + dis
// also re-zeroes d_cnt (restores the zero-on-entry invariant, since fill no longer drains it)
__global__ __launch_bounds__(1024) void k_scan() {
    __shared__ int sh[1024];
    __shared__ int s_ws[32];
    __shared__ int s_total;
    __shared__ int s_prefix;
    int b = blockIdx.x, t = threadIdx.x;
    int i = b * 1024 + t;
    int c = d_cnt[i];
    d_cnt[i] = 0;
    d_dis[i] = rsqrtf(1.0f + (float)c);

    // block total
    int v = c;
#pragma unroll
    for (int o = 16; o; o >>= 1) v += __shfl_down_sync(~0u, v, o);
    if ((t & 31) == 0) s_ws[t >> 5] = v;
    __syncthreads();
    if (t < 32) {
        int w = s_ws[t];
#pragma unroll
        for (int o = 16; o; o >>= 1) w += __shfl_down_sync(~0u, w, o);
        if (t == 0) {
            s_total = w;
            unsigned long long pub = (b == 0) ? (LB_PRE | (unsigned)w) : (LB_AGG | (unsigned)w);
            atomicExch(&d_lb[b], pub);
        }
    }
    // in-block inclusive scan
    sh[t] = c;
    __syncthreads();
    for (int o = 1; o < 1024; o <<= 1) {
        int u = (t >= o) ? sh[t - o] : 0;
        __syncthreads();
        sh[t] += u;
        __syncthreads();
    }
    // lookback by warp 0 (all 98 blocks co-resident: <=148 SMs, no deadlock)
    if (b == 0) {
        if (t == 0) s_prefix = 0;
    } else if (t < 32) {
        int running = 0;
        int look = b - 1;
        while (true) {
            int my = look - t;
            int st = 2; unsigned val = 0;
            if (my >= 0) {
                unsigned long long vv;
                do { vv = *(volatile unsigned long long*)&d_lb[my]; }
                while ((vv >> 32) == 0);
                st = (int)(vv >> 32);
                val = (unsigned)vv;
            }
            unsigned ball = __ballot_sync(~0u, st == 2);
            if (ball) {
                int fl = __ffs(ball) - 1;
                int contrib = (t <= fl) ? (int)val : 0;
#pragma unroll
                for (int o = 16; o; o >>= 1) contrib += __shfl_down_sync(~0u, contrib, o);
                if (t == 0) {
                    s_prefix = running + contrib;
                    atomicExch(&d_lb[b], LB_PRE | (unsigned)(s_prefix + s_total));
                }
                break;
            } else {
                int contrib = (int)val;
#pragma unroll
                for (int o = 16; o; o >>= 1) contrib += __shfl_down_sync(~0u, contrib, o);
                running += __shfl_sync(~0u, contrib, 0);
                look -= 32;
            }
        }
    }
    __syncthreads();
    d_rowstart[i] = s_prefix + sh[t] - c;
    if (b == NBLK - 1 && t == 1023) d_rowstart[NPAD] = s_prefix + sh[1023];
}

// atomic-free fill: pos = rowstart[dst] + precomputed rank
__global__ void k_fill(const int* __restrict__ ei, int E, int N) {
    int e = blockIdx.x * blockDim.x + threadIdx.x;
    if (e < E) {
        int s = ei[e];
        unsigned d = (unsigned)ei[E + e];
        if (d < (unsigned)N) {
            d_csr[d_rowstart[d] + d_rank[e]] = s;
        }
    }
}

// ---------------- GEMM1: h1 = x(Nx128) @ W1(128x64) -> d_gh fp16 (raw) ----------------
__global__ __launch_bounds__(256)
void k_gemm1(const float* __restrict__ A, const float* __restrict__ W, int N) {
    constexpr int K   = 128;
    constexpr int KC  = 64;
    constexpr int AST = 72;
    constexpr int BST = 72;
    constexpr int CST = 68;
    constexpr int SZ_AB = (128 * AST + 64 * BST) * 2;
    constexpr int SZ_C  = 128 * CST * 4;
    __shared__ __align__(16) char sm[SZ_C > SZ_AB ? SZ_C : SZ_AB];

    __half* As = (__half*)sm;
    __half* Ws = (__half*)(sm + 128 * AST * 2);
    float*  Cs = (float*)sm;

    const int t = threadIdx.x;
    const int w = t >> 5;
    const int rowBase = blockIdx.x * 128;

    wmma::fragment<wmma::accumulator, 16, 16, 16, float> acc[4];
#pragma unroll
    for (int j = 0; j < 4; j++) wmma::fill_fragment(acc[j], 0.0f);

    for (int kc = 0; kc < K; kc += KC) {
        __syncthreads();
#pragma unroll
        for (int i = 0; i < 8; i++) {
            int lin = i * 256 + t;
            int r = lin >> 4, f4 = lin & 15;
            int row = rowBase + r;
            float4 v = make_float4(0.f, 0.f, 0.f, 0.f);
            if (row < N) v = *(const float4*)&A[(size_t)row * K + kc + f4 * 4];
            *(__half2*)&As[r * AST + f4 * 4]     = __floats2half2_rn(v.x, v.y);
            *(__half2*)&As[r * AST + f4 * 4 + 2] = __floats2half2_rn(v.z, v.w);
        }
#pragma unroll
        for (int i = 0; i < 4; i++) {
            int lin = i * 256 + t;
            int k = lin >> 4, f4 = lin & 15;
            float4 v = *(const float4*)&W[(size_t)(kc + k) * 64 + f4 * 4];
            Ws[(f4 * 4 + 0) * BST + k] = __float2half(v.x);
            Ws[(f4 * 4 + 1) * BST + k] = __float2half(v.y);
            Ws[(f4 * 4 + 2) * BST + k] = __float2half(v.z);
            Ws[(f4 * 4 + 3) * BST + k] = __float2half(v.w);
        }
        __syncthreads();

#pragma unroll
        for (int kk = 0; kk < KC; kk += 16) {
            wmma::fragment<wmma::matrix_a, 16, 16, 16, __half, wmma::row_major> af;
            wmma::load_matrix_sync(af, As + w * 16 * AST + kk, AST);
#pragma unroll
            for (int j = 0; j < 4; j++) {
                wmma::fragment<wmma::matrix_b, 16, 16, 16, __half, wmma::col_major> bf;
                wmma::load_matrix_sync(bf, Ws + j * 16 * BST + kk, BST);
                wmma::mma_sync(acc[j], af, bf, acc[j]);
            }
        }
    }

    __syncthreads();
#pragma unroll
    for (int j = 0; j < 4; j++)
        wmma::store_matrix_sync(Cs + w * 16 * CST + j * 16, acc[j], CST, wmma::mem_row_major);
    __syncthreads();

#pragma unroll
    for (int i = 0; i < 8; i++) {
        int lin = i * 256 + t;
        int r = lin >> 4, f4 = lin & 15;
        float4 v = *(const float4*)&Cs[r * CST + f4 * 4];
        __half2 h0 = __floats2half2_rn(v.x, v.y);
        __half2 h1 = __floats2half2_rn(v.z, v.w);
        uint2 u;
        u.x = *(unsigned*)&h0; u.y = *(unsigned*)&h1;
        *(uint2*)&d_gh[(size_t)(rowBase + r) * 64 + f4 * 4] = u;
    }
}

// ---------------- fused gather(layer1) + GEMM2 -> d_gh2 = (relu(agg1+b1) @ W2) * dis ----------------
__global__ __launch_bounds__(256)
void k_gg2(const float* __restrict__ W, const float* __restrict__ b1) {
    constexpr int AST = 72;
    constexpr int BST = 72;
    constexpr int CST = 68;
    constexpr int SZ_AB = (128 * AST + 64 * BST) * 2;
    constexpr int SZ_C  = 128 * CST * 4;
    __shared__ __align__(16) char sm[SZ_C > SZ_AB ? SZ_C : SZ_AB];

    __half* As = (__half*)sm;
    __half* Ws = (__half*)(sm + 128 * AST * 2);
    float*  Cs = (float*)sm;

    const int t = threadIdx.x;
    const int w = t >> 5;
    const int lane = t & 31;
    const int sub = lane >> 3;
    const int c = (lane & 7) * 8;
    const int rowBase = blockIdx.x * 128;

    float bb[8];
    {
        float4 b0 = *(const float4*)&b1[c];
        float4 b4 = *(const float4*)&b1[c + 4];
        bb[0]=b0.x; bb[1]=b0.y; bb[2]=b0.z; bb[3]=b0.w;
        bb[4]=b4.x; bb[5]=b4.y; bb[6]=b4.z; bb[7]=b4.w;
    }

#pragma unroll 1
    for (int pass = 0; pass < 4; pass++) {
        int r = pass * 32 + w * 4 + sub;
        int node = rowBase + r;
        int beg = d_rowstart[node];
        int end = d_rowstart[node + 1];
        float dn = d_dis[node];
        float acc[8];
        {
            uint4 u = *(const uint4*)&d_gh[(size_t)node * 64 + c];
            const __half2* h = (const __half2*)&u;
#pragma unroll
            for (int i = 0; i < 4; i++) {
                float2 f = __half22float2(h[i]);
                acc[i * 2] = f.x * dn; acc[i * 2 + 1] = f.y * dn;
            }
        }
        int e = beg;
        for (; e + 3 < end; e += 4) {
            int s0 = d_csr[e], s1 = d_csr[e + 1], s2 = d_csr[e + 2], s3 = d_csr[e + 3];
            float ds0 = d_dis[s0], ds1 = d_dis[s1], ds2 = d_dis[s2], ds3 = d_dis[s3];
            uint4 u0 = *(const uint4*)&d_gh[(size_t)s0 * 64 + c];
            uint4 u1 = *(const uint4*)&d_gh[(size_t)s1 * 64 + c];
            uint4 u2 = *(const uint4*)&d_gh[(size_t)s2 * 64 + c];
            uint4 u3 = *(const uint4*)&d_gh[(size_t)s3 * 64 + c];
            const __half2* h0 = (const __half2*)&u0;
            const __half2* h1 = (const __half2*)&u1;
            const __half2* h2 = (const __half2*)&u2;
            const __half2* h3 = (const __half2*)&u3;
#pragma unroll
            for (int i = 0; i < 4; i++) {
                float2 f0 = __half22float2(h0[i]);
                float2 f1 = __half22float2(h1[i]);
                float2 f2 = __half22float2(h2[i]);
                float2 f3 = __half22float2(h3[i]);
                acc[i * 2]     += f0.x * ds0 + f1.x * ds1 + f2.x * ds2 + f3.x * ds3;
                acc[i * 2 + 1] += f0.y * ds0 + f1.y * ds1 + f2.y * ds2 + f3.y * ds3;
            }
        }
        for (; e < end; e++) {
            int s0 = d_csr[e];
            float ds0 = d_dis[s0];
            uint4 u0 = *(const uint4*)&d_gh[(size_t)s0 * 64 + c];
            const __half2* h0 = (const __half2*)&u0;
#pragma unroll
            for (int i = 0; i < 4; i++) {
                float2 f0 = __half22float2(h0[i]);
                acc[i * 2]     += f0.x * ds0;
                acc[i * 2 + 1] += f0.y * ds0;
            }
        }
        __half2 hh[4];
#pragma unroll
        for (int i = 0; i < 4; i++)
            hh[i] = __floats2half2_rn(fmaxf(acc[i * 2] * dn + bb[i * 2], 0.f),
                                      fmaxf(acc[i * 2 + 1] * dn + bb[i * 2 + 1], 0.f));
        *(uint4*)&As[r * AST + c] = *(uint4*)hh;
    }

#pragma unroll
    for (int i = 0; i < 4; i++) {
        int lin = i * 256 + t;
        int k = lin >> 4, f4 = lin & 15;
        float4 v = *(const float4*)&W[(size_t)k * 64 + f4 * 4];
        Ws[(f4 * 4 + 0) * BST + k] = __float2half(v.x);
        Ws[(f4 * 4 + 1) * BST + k] = __float2half(v.y);
        Ws[(f4 * 4 + 2) * BST + k] = __float2half(v.z);
        Ws[(f4 * 4 + 3) * BST + k] = __float2half(v.w);
    }
    __syncthreads();

    wmma::fragment<wmma::accumulator, 16, 16, 16, float> acc[4];
#pragma unroll
    for (int j = 0; j < 4; j++) wmma::fill_fragment(acc[j], 0.0f);

#pragma unroll
    for (int kk = 0; kk < 64; kk += 16) {
        wmma::fragment<wmma::matrix_a, 16, 16, 16, __half, wmma::row_major> af;
        wmma::load_matrix_sync(af, As + w * 16 * AST + kk, AST);
#pragma unroll
        for (int j = 0; j < 4; j++) {
            wmma::fragment<wmma::matrix_b, 16, 16, 16, __half, wmma::col_major> bf;
            wmma::load_matrix_sync(bf, Ws + j * 16 * BST + kk, BST);
            wmma::mma_sync(acc[j], af, bf, acc[j]);
        }
    }

    __syncthreads();
#pragma unroll
    for (int j = 0; j < 4; j++)
        wmma::store_matrix_sync(Cs + w * 16 * CST + j * 16, acc[j], CST, wmma::mem_row_major);
    __syncthreads();

#pragma unroll
    for (int i = 0; i < 8; i++) {
        int lin = i * 256 + t;
        int r = lin >> 4, f4 = lin & 15;
        float dn = d_dis[rowBase + r];
        float4 v = *(const float4*)&Cs[r * CST + f4 * 4];
        __half2 h0 = __floats2half2_rn(v.x * dn, v.y * dn);
        __half2 h1 = __floats2half2_rn(v.z * dn, v.w * dn);
        uint2 u;
        u.x = *(unsigned*)&h0; u.y = *(unsigned*)&h1;
        *(uint2*)&d_gh2[(size_t)(rowBase + r) * 64 + f4 * 4] = u;
    }
}

// ---------------- fused gather(layer2) + layer3 dot; gh2 premultiplied by dis ----------------
__global__ void k_g2l3(const float* __restrict__ W3, const float* __restrict__ b2v,
                       const float* __restrict__ b3, float* __restrict__ out, int N) {
    int idx = blockIdx.x * blockDim.x + threadIdx.x;
    int node = idx >> 3;
    if (node >= N) return;
    int lane = idx & 7;
    int c = lane * 8;
    float w3[8], bb[8];
    {
        float4 a = *(const float4*)&W3[c];
        float4 b = *(const float4*)&W3[c + 4];
        w3[0]=a.x; w3[1]=a.y; w3[2]=a.z; w3[3]=a.w;
        w3[4]=b.x; w3[5]=b.y; w3[6]=b.z; w3[7]=b.w;
        float4 p = *(const float4*)&b2v[c];
        float4 q = *(const float4*)&b2v[c + 4];
        bb[0]=p.x; bb[1]=p.y; bb[2]=p.z; bb[3]=p.w;
        bb[4]=q.x; bb[5]=q.y; bb[6]=q.z; bb[7]=q.w;
    }
    int beg = d_rowstart[node];
    int end = d_rowstart[node + 1];
    float dn = d_dis[node];
    float acc[8];
    {
        uint4 u = *(const uint4*)&d_gh2[(size_t)node * 64 + c];
        const __half2* h = (const __half2*)&u;
#pragma unroll
        for (int i = 0; i < 4; i++) {
            float2 f = __half22float2(h[i]);
            acc[i * 2] = f.x; acc[i * 2 + 1] = f.y;
        }
    }
    int e = beg;
    for (; e + 3 < end; e += 4) {
        int s0 = d_csr[e], s1 = d_csr[e + 1], s2 = d_csr[e + 2], s3 = d_csr[e + 3];
        uint4 u0 = *(const uint4*)&d_gh2[(size_t)s0 * 64 + c];
        uint4 u1 = *(const uint4*)&d_gh2[(size_t)s1 * 64 + c];
        uint4 u2 = *(const uint4*)&d_gh2[(size_t)s2 * 64 + c];
        uint4 u3 = *(const uint4*)&d_gh2[(size_t)s3 * 64 + c];
        const __half2* h0 = (const __half2*)&u0;
        const __half2* h1 = (const __half2*)&u1;
        const __half2* h2 = (const __half2*)&u2;
        const __half2* h3 = (const __half2*)&u3;
#pragma unroll
        for (int i = 0; i < 4; i++) {
            float2 f0 = __half22float2(h0[i]);
            float2 f1 = __half22float2(h1[i]);
            float2 f2 = __half22float2(h2[i]);
            float2 f3 = __half22float2(h3[i]);
            acc[i * 2]     += (f0.x + f1.x) + (f2.x + f3.x);
            acc[i * 2 + 1] += (f0.y + f1.y) + (f2.y + f3.y);
        }
    }
    for (; e < end; e++) {
        int s0 = d_csr[e];
        uint4 u0 = *(const uint4*)&d_gh2[(size_t)s0 * 64 + c];
        const __half2* h0 = (const __half2*)&u0;
#pragma unroll
        for (int i = 0; i < 4; i++) {
            float2 f0 = __half22float2(h0[i]);
            acc[i * 2]     += f0.x;
            acc[i * 2 + 1] += f0.y;
        }
    }
    float s = 0.f;
#pragma unroll
    for (int i = 0; i < 8; i++)
        s += fmaxf(acc[i] * dn + bb[i], 0.f) * w3[i];
    unsigned mask = 0xFFu << (threadIdx.x & 24);
    s += __shfl_xor_sync(mask, s, 1);
    s += __shfl_xor_sync(mask, s, 2);
    s += __shfl_xor_sync(mask, s, 4);
    if (lane == 0) {
        d_g3[node] = s * dn;
        out[node]  = s * dn * dn + b3[0];
    }
}

__global__ void k_gather_out(float* __restrict__ out, int N) {
    int i = blockIdx.x * blockDim.x + threadIdx.x;
    if (i >= N) return;
    int beg = d_rowstart[i];
    int end = d_rowstart[i + 1];
    float s0 = 0.f, s1 = 0.f, s2 = 0.f, s3 = 0.f;
    int e = beg;
    for (; e + 3 < end; e += 4) {
        s0 += d_g3[d_csr[e]];
        s1 += d_g3[d_csr[e + 1]];
        s2 += d_g3[d_csr[e + 2]];
        s3 += d_g3[d_csr[e + 3]];
    }
    for (; e < end; e++) s0 += d_g3[d_csr[e]];
    out[i] += ((s0 + s1) + (s2 + s3)) * d_dis[i];
}

// ---------------- launch ----------------
extern "C" void kernel_launch(void* const* d_in, const int* in_sizes, int n_in,
                              void* d_out, int out_size) {
    const float* x  = (const float*)d_in[0];
    const int*   ei = (const int*)d_in[1];        // int32 (JAX x64 disabled)
    const float* W1 = (const float*)d_in[2];
    const float* b1 = (const float*)d_in[3];
    const float* W2 = (const float*)d_in[4];
    const float* b2 = (const float*)d_in[5];
    const float* W3 = (const float*)d_in[6];
    const float* b3 = (const float*)d_in[7];
    float* out = (float*)d_out;

    int N = in_sizes[0] / 128;
    int E = in_sizes[1] / 2;

    static cudaStream_t s2 = nullptr;
    static cudaEvent_t ev_fork = nullptr, ev_gemm = nullptr;
    if (!s2) {
        cudaStreamCreateWithFlags(&s2, cudaStreamNonBlocking);
        cudaEventCreateWithFlags(&ev_fork, cudaEventDisableTiming);
        cudaEventCreateWithFlags(&ev_gemm, cudaEventDisableTiming);
    }

    const int gblocks = NPAD / 128;

    // fork: GEMM1 (independent of graph preprocessing) on s2
    cudaEventRecord(ev_fork, 0);
    cudaStreamWaitEvent(s2, ev_fork, 0);
    k_gemm1<<<gblocks, 256, 0, s2>>>(x, W1, N);
    cudaEventRecord(ev_gemm, s2);

    // preprocessing on the main stream: CSR by dst + norms
    k_count<<<(E + 255) / 256, 256>>>(ei, E, N);
    k_scan<<<NBLK, 1024>>>();
    k_fill<<<(E + 255) / 256, 256>>>(ei, E, N);

    // join, then fused layer-1 aggregation + layer-2 transform
    cudaStreamWaitEvent(0, ev_gemm, 0);
    k_gg2<<<gblocks, 256>>>(W2, b1);

    // fused layer-2 aggregation + layer-3 transform
    k_g2l3<<<(N * 8 + 255) / 256, 256>>>(W3, b2, b3, out, N);

    // layer-3 aggregation
    k_gather_out<<<(N + 255) / 256, 256>>>(out, N);
}

// round 12
// speedup vs baseline: 1.0329x; 1.0329x over previous
#include <cuda_runtime.h>
#include <cuda_fp16.h>
#include <mma.h>

using namespace nvcuda;

#define NMAX  100000
#define NPAD  100352        // 1024 * 98, multiple of 128
#define NBLK  98            // NPAD / 1024
#define EMAX  1600000
#define HID   64

#define LB_AGG (1ULL << 32)
#define LB_PRE (2ULL << 32)

// ---------------- scratch (device globals; no allocation) ----------------
__device__ __align__(16) float  d_dis[NPAD];          // deg_inv_sqrt
__device__ __align__(16) __half d_gh[NPAD * HID];     // layer-1 h; premultiplied by dis after k_premult
__device__ __align__(16) __half d_gh2[NPAD * HID];    // layer-2 h * dis (premultiplied)
__device__ __align__(16) float  d_g3[NPAD];           // layer-3 h*dis
__device__ int d_csr[EMAX];                           // src ids grouped by dst
__device__ int d_rank[EMAX];                          // per-edge rank within its dst
__device__ int d_cnt[NPAD];                           // indegree (zero-init; scan re-zeroes)
__device__ int d_rowstart[NPAD + 1];                  // exclusive prefix of cnt
__device__ unsigned long long d_lb[NBLK];             // decoupled-lookback state

// ---------------- preprocessing ----------------
// count + rank, 4 edges per thread (int4)
__global__ void k_count(const int* __restrict__ ei, int E, int N) {
    if (blockIdx.x == 0 && threadIdx.x < NBLK) d_lb[threadIdx.x] = 0;   // reset lookback state
    int base = (blockIdx.x * blockDim.x + threadIdx.x) * 4;
    if (base + 3 < E) {
        int4 d4 = *(const int4*)&ei[E + base];
        int4 r;
        r.x = ((unsigned)d4.x < (unsigned)N) ? atomicAdd(&d_cnt[d4.x], 1) : 0;
        r.y = ((unsigned)d4.y < (unsigned)N) ? atomicAdd(&d_cnt[d4.y], 1) : 0;
        r.z = ((unsigned)d4.z < (unsigned)N) ? atomicAdd(&d_cnt[d4.z], 1) : 0;
        r.w = ((unsigned)d4.w < (unsigned)N) ? atomicAdd(&d_cnt[d4.w], 1) : 0;
        *(int4*)&d_rank[base] = r;
    } else if (base < E) {
        for (int e = base; e < E; e++) {
            unsigned d = (unsigned)ei[E + e];
            d_rank[e] = (d < (unsigned)N) ? atomicAdd(&d_cnt[(int)d], 1) : 0;
        }
    }
}

// single-pass scan (shfl-based): reduce+publish -> in-block scan -> lookback -> rowstart + dis
// also re-zeroes d_cnt (restores the zero-on-entry invariant)
__global__ __launch_bounds__(1024) void k_scan() {
    __shared__ int s_warp[32];
    __shared__ int s_prefix;
    int b = blockIdx.x, t = threadIdx.x;
    int i = b * 1024 + t;
    int c = d_cnt[i];
    d_cnt[i] = 0;
    d_dis[i] = rsqrtf(1.0f + (float)c);
    int lane = t & 31, wid = t >> 5;

    // warp inclusive scan
    int x = c;
#pragma unroll
    for (int o = 1; o < 32; o <<= 1) {
        int y = __shfl_up_sync(~0u, x, o);
        if (lane >= o) x += y;
    }
    if (lane == 31) s_warp[wid] = x;
    __syncthreads();
    if (t < 32) {
        int y = s_warp[t];
#pragma unroll
        for (int o = 1; o < 32; o <<= 1) {
            int z = __shfl_up_sync(~0u, y, o);
            if (t >= o) y += z;
        }
        s_warp[t] = y;
        if (t == 31) {   // publish block total
            unsigned long long pub = (b == 0) ? (LB_PRE | (unsigned)y) : (LB_AGG | (unsigned)y);
            atomicExch(&d_lb[b], pub);
        }
    }
    __syncthreads();
    int incl = x + (wid ? s_warp[wid - 1] : 0);
    int total = s_warp[31];

    // lookback by warp 0 (all 98 blocks co-resident on 148 SMs: no deadlock)
    if (b == 0) {
        if (t == 0) s_prefix = 0;
    } else if (t < 32) {
        int running = 0;
        int look = b - 1;
        while (true) {
            int my = look - t;
            int st = 2; unsigned val = 0;
            if (my >= 0) {
                unsigned long long vv;
                do { vv = *(volatile unsigned long long*)&d_lb[my]; }
                while ((vv >> 32) == 0);
                st = (int)(vv >> 32);
                val = (unsigned)vv;
            }
            unsigned ball = __ballot_sync(~0u, st == 2);
            if (ball) {
                int fl = __ffs(ball) - 1;
                int contrib = (t <= fl) ? (int)val : 0;
#pragma unroll
                for (int o = 16; o; o >>= 1) contrib += __shfl_down_sync(~0u, contrib, o);
                if (t == 0) {
                    s_prefix = running + contrib;
                    atomicExch(&d_lb[b], LB_PRE | (unsigned)(s_prefix + total));
                }
                break;
            } else {
                int contrib = (int)val;
#pragma unroll
                for (int o = 16; o; o >>= 1) contrib += __shfl_down_sync(~0u, contrib, o);
                running += __shfl_sync(~0u, contrib, 0);
                look -= 32;
            }
        }
    }
    __syncthreads();
    d_rowstart[i] = s_prefix + incl - c;
    if (b == NBLK - 1 && t == 1023) d_rowstart[NPAD] = s_prefix + incl;
}

// atomic-free fill, 4 edges per thread
__global__ void k_fill(const int* __restrict__ ei, int E, int N) {
    int base = (blockIdx.x * blockDim.x + threadIdx.x) * 4;
    if (base + 3 < E) {
        int4 s4 = *(const int4*)&ei[base];
        int4 d4 = *(const int4*)&ei[E + base];
        int4 r4 = *(const int4*)&d_rank[base];
        if ((unsigned)d4.x < (unsigned)N) d_csr[d_rowstart[d4.x] + r4.x] = s4.x;
        if ((unsigned)d4.y < (unsigned)N) d_csr[d_rowstart[d4.y] + r4.y] = s4.y;
        if ((unsigned)d4.z < (unsigned)N) d_csr[d_rowstart[d4.z] + r4.z] = s4.z;
        if ((unsigned)d4.w < (unsigned)N) d_csr[d_rowstart[d4.w] + r4.w] = s4.w;
    } else if (base < E) {
        for (int e = base; e < E; e++) {
            unsigned d = (unsigned)ei[E + e];
            if (d < (unsigned)N) d_csr[d_rowstart[d] + d_rank[e]] = ei[e];
        }
    }
}

// ---------------- GEMM1: h1 = x(Nx128) @ W1(128x64) -> d_gh fp16 (raw h) ----------------
// W loaded once (full K); accumulators stored straight to global as fp16 (no smem C).
__global__ __launch_bounds__(256)
void k_gemm1(const float* __restrict__ A, const float* __restrict__ W, int N) {
    constexpr int K   = 128;
    constexpr int KC  = 64;
    constexpr int AST = 72;     // A chunk stride (halfs)
    constexpr int BST = 136;    // W stride (halfs), full K
    __shared__ __align__(16) __half As[128 * AST];   // 18432 B
    __shared__ __align__(16) __half Ws[64 * BST];    // 17408 B

    const int t = threadIdx.x;
    const int w = t >> 5;
    const int rowBase = blockIdx.x * 128;

    // load full W (128k x 64n) -> col-major Ws[n*BST + k]; 2048 float4, 8 per thread
#pragma unroll
    for (int i = 0; i < 8; i++) {
        int lin = i * 256 + t;
        int k = lin >> 4, f4 = lin & 15;
        float4 v = *(const float4*)&W[(size_t)k * 64 + f4 * 4];
        Ws[(f4 * 4 + 0) * BST + k] = __float2half(v.x);
        Ws[(f4 * 4 + 1) * BST + k] = __float2half(v.y);
        Ws[(f4 * 4 + 2) * BST + k] = __float2half(v.z);
        Ws[(f4 * 4 + 3) * BST + k] = __float2half(v.w);
    }

    wmma::fragment<wmma::accumulator, 16, 16, 16, float> acc[4];
#pragma unroll
    for (int j = 0; j < 4; j++) wmma::fill_fragment(acc[j], 0.0f);

    for (int kc = 0; kc < K; kc += KC) {
        __syncthreads();
#pragma unroll
        for (int i = 0; i < 8; i++) {
            int lin = i * 256 + t;
            int r = lin >> 4, f4 = lin & 15;
            int row = rowBase + r;
            float4 v = make_float4(0.f, 0.f, 0.f, 0.f);
            if (row < N) v = *(const float4*)&A[(size_t)row * K + kc + f4 * 4];
            *(__half2*)&As[r * AST + f4 * 4]     = __floats2half2_rn(v.x, v.y);
            *(__half2*)&As[r * AST + f4 * 4 + 2] = __floats2half2_rn(v.z, v.w);
        }
        __syncthreads();

#pragma unroll
        for (int kk = 0; kk < KC; kk += 16) {
            wmma::fragment<wmma::matrix_a, 16, 16, 16, __half, wmma::row_major> af;
            wmma::load_matrix_sync(af, As + w * 16 * AST + kk, AST);
#pragma unroll
            for (int j = 0; j < 4; j++) {
                wmma::fragment<wmma::matrix_b, 16, 16, 16, __half, wmma::col_major> bf;
                wmma::load_matrix_sync(bf, Ws + j * 16 * BST + kc + kk, BST);
                wmma::mma_sync(acc[j], af, bf, acc[j]);
            }
        }
    }

    // direct fp16 store: elementwise convert acc fragment -> half fragment, store to global
#pragma unroll
    for (int j = 0; j < 4; j++) {
        wmma::fragment<wmma::accumulator, 16, 16, 16, __half> hf;
#pragma unroll
        for (int q = 0; q < hf.num_elements; q++) hf.x[q] = __float2half(acc[j].x[q]);
        wmma::store_matrix_sync(&d_gh[(size_t)(rowBase + w * 16) * 64 + j * 16],
                                hf, 64, wmma::mem_row_major);
    }
}

// ---------------- premult: gh *= dis (row-wise), on the s2 leg after gemm1 & scan ----------------
__global__ void k_premult() {
    int idx = blockIdx.x * blockDim.x + threadIdx.x;   // one uint4 = 8 halfs
    if (idx >= NPAD * 8) return;
    int row = idx >> 3;
    float dn = d_dis[row];
    uint4 u = *(const uint4*)&d_gh[(size_t)idx * 8];
    __half2* h = (__half2*)&u;
#pragma unroll
    for (int i = 0; i < 4; i++) {
        float2 f = __half22float2(h[i]);
        h[i] = __floats2half2_rn(f.x * dn, f.y * dn);
    }
    *(uint4*)&d_gh[(size_t)idx * 8] = u;
}

// ---------------- fused gather(layer1) + GEMM2 -> d_gh2 = (relu(dn*acc + b1) @ W2) * dis ----------------
// gh is premultiplied: acc = gh[node] + sum_s gh[s]  (no per-edge dis!)
__global__ __launch_bounds__(256)
void k_gg2(const float* __restrict__ W, const float* __restrict__ b1) {
    constexpr int AST = 72;
    constexpr int BST = 72;
    constexpr int CST = 68;
    constexpr int SZ_AB = (128 * AST + 64 * BST) * 2;
    constexpr int SZ_C  = 128 * CST * 4;
    __shared__ __align__(16) char sm[SZ_C > SZ_AB ? SZ_C : SZ_AB];

    __half* As = (__half*)sm;
    __half* Ws = (__half*)(sm + 128 * AST * 2);
    float*  Cs = (float*)sm;

    const int t = threadIdx.x;
    const int w = t >> 5;
    const int lane = t & 31;
    const int sub = lane >> 3;
    const int c = (lane & 7) * 8;
    const int rowBase = blockIdx.x * 128;

    float bb[8];
    {
        float4 b0 = *(const float4*)&b1[c];
        float4 b4 = *(const float4*)&b1[c + 4];
        bb[0]=b0.x; bb[1]=b0.y; bb[2]=b0.z; bb[3]=b0.w;
        bb[4]=b4.x; bb[5]=b4.y; bb[6]=b4.z; bb[7]=b4.w;
    }

#pragma unroll 1
    for (int pass = 0; pass < 4; pass++) {
        int r = pass * 32 + w * 4 + sub;
        int node = rowBase + r;
        int beg = d_rowstart[node];
        int end = d_rowstart[node + 1];
        float dn = d_dis[node];
        float acc[8];
        {
            uint4 u = *(const uint4*)&d_gh[(size_t)node * 64 + c];   // self term (already *dn)
            const __half2* h = (const __half2*)&u;
#pragma unroll
            for (int i = 0; i < 4; i++) {
                float2 f = __half22float2(h[i]);
                acc[i * 2] = f.x; acc[i * 2 + 1] = f.y;
            }
        }
        int e = beg;
        for (; e + 3 < end; e += 4) {
            int s0 = d_csr[e], s1 = d_csr[e + 1], s2 = d_csr[e + 2], s3 = d_csr[e + 3];
            uint4 u0 = *(const uint4*)&d_gh[(size_t)s0 * 64 + c];
            uint4 u1 = *(const uint4*)&d_gh[(size_t)s1 * 64 + c];
            uint4 u2 = *(const uint4*)&d_gh[(size_t)s2 * 64 + c];
            uint4 u3 = *(const uint4*)&d_gh[(size_t)s3 * 64 + c];
            const __half2* h0 = (const __half2*)&u0;
            const __half2* h1 = (const __half2*)&u1;
            const __half2* h2 = (const __half2*)&u2;
            const __half2* h3 = (const __half2*)&u3;
#pragma unroll
            for (int i = 0; i < 4; i++) {
                float2 f0 = __half22float2(h0[i]);
                float2 f1 = __half22float2(h1[i]);
                float2 f2 = __half22float2(h2[i]);
                float2 f3 = __half22float2(h3[i]);
                acc[i * 2]     += (f0.x + f1.x) + (f2.x + f3.x);
                acc[i * 2 + 1] += (f0.y + f1.y) + (f2.y + f3.y);
            }
        }
        for (; e < end; e++) {
            int s0 = d_csr[e];
            uint4 u0 = *(const uint4*)&d_gh[(size_t)s0 * 64 + c];
            const __half2* h0 = (const __half2*)&u0;
#pragma unroll
            for (int i = 0; i < 4; i++) {
                float2 f0 = __half22float2(h0[i]);
                acc[i * 2]     += f0.x;
                acc[i * 2 + 1] += f0.y;
            }
        }
        __half2 hh[4];
#pragma unroll
        for (int i = 0; i < 4; i++)
            hh[i] = __floats2half2_rn(fmaxf(acc[i * 2] * dn + bb[i * 2], 0.f),
                                      fmaxf(acc[i * 2 + 1] * dn + bb[i * 2 + 1], 0.f));
        *(uint4*)&As[r * AST + c] = *(uint4*)hh;
    }

#pragma unroll
    for (int i = 0; i < 4; i++) {
        int lin = i * 256 + t;
        int k = lin >> 4, f4 = lin & 15;
        float4 v = *(const float4*)&W[(size_t)k * 64 + f4 * 4];
        Ws[(f4 * 4 + 0) * BST + k] = __float2half(v.x);
        Ws[(f4 * 4 + 1) * BST + k] = __float2half(v.y);
        Ws[(f4 * 4 + 2) * BST + k] = __float2half(v.z);
        Ws[(f4 * 4 + 3) * BST + k] = __float2half(v.w);
    }
    __syncthreads();

    wmma::fragment<wmma::accumulator, 16, 16, 16, float> acc[4];
#pragma unroll
    for (int j = 0; j < 4; j++) wmma::fill_fragment(acc[j], 0.0f);

#pragma unroll
    for (int kk = 0; kk < 64; kk += 16) {
        wmma::fragment<wmma::matrix_a, 16, 16, 16, __half, wmma::row_major> af;
        wmma::load_matrix_sync(af, As + w * 16 * AST + kk, AST);
#pragma unroll
        for (int j = 0; j < 4; j++) {
            wmma::fragment<wmma::matrix_b, 16, 16, 16, __half, wmma::col_major> bf;
            wmma::load_matrix_sync(bf, Ws + j * 16 * BST + kk, BST);
            wmma::mma_sync(acc[j], af, bf, acc[j]);
        }
    }

    __syncthreads();
#pragma unroll
    for (int j = 0; j < 4; j++)
        wmma::store_matrix_sync(Cs + w * 16 * CST + j * 16, acc[j], CST, wmma::mem_row_major);
    __syncthreads();

    // epilogue: gh2 = h2 * dis (premultiplied for the next gather)
#pragma unroll
    for (int i = 0; i < 8; i++) {
        int lin = i * 256 + t;
        int r = lin >> 4, f4 = lin & 15;
        float dn = d_dis[rowBase + r];
        float4 v = *(const float4*)&Cs[r * CST + f4 * 4];
        __half2 h0 = __floats2half2_rn(v.x * dn, v.y * dn);
        __half2 h1 = __floats2half2_rn(v.z * dn, v.w * dn);
        uint2 u;
        u.x = *(unsigned*)&h0; u.y = *(unsigned*)&h1;
        *(uint2*)&d_gh2[(size_t)(rowBase + r) * 64 + f4 * 4] = u;
    }
}

// ---------------- fused gather(layer2) + layer3 dot; gh2 premultiplied by dis ----------------
__global__ void k_g2l3(const float* __restrict__ W3, const float* __restrict__ b2v,
                       const float* __restrict__ b3, float* __restrict__ out, int N) {
    int idx = blockIdx.x * blockDim.x + threadIdx.x;
    int node = idx >> 3;
    if (node >= N) return;
    int lane = idx & 7;
    int c = lane * 8;
    float w3[8], bb[8];
    {
        float4 a = *(const float4*)&W3[c];
        float4 b = *(const float4*)&W3[c + 4];
        w3[0]=a.x; w3[1]=a.y; w3[2]=a.z; w3[3]=a.w;
        w3[4]=b.x; w3[5]=b.y; w3[6]=b.z; w3[7]=b.w;
        float4 p = *(const float4*)&b2v[c];
        float4 q = *(const float4*)&b2v[c + 4];
        bb[0]=p.x; bb[1]=p.y; bb[2]=p.z; bb[3]=p.w;
        bb[4]=q.x; bb[5]=q.y; bb[6]=q.z; bb[7]=q.w;
    }
    int beg = d_rowstart[node];
    int end = d_rowstart[node + 1];
    float dn = d_dis[node];
    float acc[8];
    {
        uint4 u = *(const uint4*)&d_gh2[(size_t)node * 64 + c];
        const __half2* h = (const __half2*)&u;
#pragma unroll
        for (int i = 0; i < 4; i++) {
            float2 f = __half22float2(h[i]);
            acc[i * 2] = f.x; acc[i * 2 + 1] = f.y;
        }
    }
    int e = beg;
    for (; e + 3 < end; e += 4) {
        int s0 = d_csr[e], s1 = d_csr[e + 1], s2 = d_csr[e + 2], s3 = d_csr[e + 3];
        uint4 u0 = *(const uint4*)&d_gh2[(size_t)s0 * 64 + c];
        uint4 u1 = *(const uint4*)&d_gh2[(size_t)s1 * 64 + c];
        uint4 u2 = *(const uint4*)&d_gh2[(size_t)s2 * 64 + c];
        uint4 u3 = *(const uint4*)&d_gh2[(size_t)s3 * 64 + c];
        const __half2* h0 = (const __half2*)&u0;
        const __half2* h1 = (const __half2*)&u1;
        const __half2* h2 = (const __half2*)&u2;
        const __half2* h3 = (const __half2*)&u3;
#pragma unroll
        for (int i = 0; i < 4; i++) {
            float2 f0 = __half22float2(h0[i]);
            float2 f1 = __half22float2(h1[i]);
            float2 f2 = __half22float2(h2[i]);
            float2 f3 = __half22float2(h3[i]);
            acc[i * 2]     += (f0.x + f1.x) + (f2.x + f3.x);
            acc[i * 2 + 1] += (f0.y + f1.y) + (f2.y + f3.y);
        }
    }
    for (; e < end; e++) {
        int s0 = d_csr[e];
        uint4 u0 = *(const uint4*)&d_gh2[(size_t)s0 * 64 + c];
        const __half2* h0 = (const __half2*)&u0;
#pragma unroll
        for (int i = 0; i < 4; i++) {
            float2 f0 = __half22float2(h0[i]);
            acc[i * 2]     += f0.x;
            acc[i * 2 + 1] += f0.y;
        }
    }
    float s = 0.f;
#pragma unroll
    for (int i = 0; i < 8; i++)
        s += fmaxf(acc[i] * dn + bb[i], 0.f) * w3[i];
    unsigned mask = 0xFFu << (threadIdx.x & 24);
    s += __shfl_xor_sync(mask, s, 1);
    s += __shfl_xor_sync(mask, s, 2);
    s += __shfl_xor_sync(mask, s, 4);
    if (lane == 0) {
        d_g3[node] = s * dn;
        out[node]  = s * dn * dn + b3[0];
    }
}

__global__ void k_gather_out(float* __restrict__ out, int N) {
    int i = blockIdx.x * blockDim.x + threadIdx.x;
    if (i >= N) return;
    int beg = d_rowstart[i];
    int end = d_rowstart[i + 1];
    float s0 = 0.f, s1 = 0.f, s2 = 0.f, s3 = 0.f;
    int e = beg;
    for (; e + 3 < end; e += 4) {
        s0 += d_g3[d_csr[e]];
        s1 += d_g3[d_csr[e + 1]];
        s2 += d_g3[d_csr[e + 2]];
        s3 += d_g3[d_csr[e + 3]];
    }
    for (; e < end; e++) s0 += d_g3[d_csr[e]];
    out[i] += ((s0 + s1) + (s2 + s3)) * d_dis[i];
}

// ---------------- launch ----------------
extern "C" void kernel_launch(void* const* d_in, const int* in_sizes, int n_in,
                              void* d_out, int out_size) {
    const float* x  = (const float*)d_in[0];
    const int*   ei = (const int*)d_in[1];        // int32 (JAX x64 disabled)
    const float* W1 = (const float*)d_in[2];
    const float* b1 = (const float*)d_in[3];
    const float* W2 = (const float*)d_in[4];
    const float* b2 = (const float*)d_in[5];
    const float* W3 = (const float*)d_in[6];
    const float* b3 = (const float*)d_in[7];
    float* out = (float*)d_out;

    int N = in_sizes[0] / 128;
    int E = in_sizes[1] / 2;

    static cudaStream_t s2 = nullptr;
    static cudaEvent_t ev_fork = nullptr, ev_scan = nullptr, ev_gemm = nullptr;
    if (!s2) {
        cudaStreamCreateWithFlags(&s2, cudaStreamNonBlocking);
        cudaEventCreateWithFlags(&ev_fork, cudaEventDisableTiming);
        cudaEventCreateWithFlags(&ev_scan, cudaEventDisableTiming);
        cudaEventCreateWithFlags(&ev_gemm, cudaEventDisableTiming);
    }

    const int gblocks = NPAD / 128;
    const int qedge_blocks = ((E + 3) / 4 + 255) / 256;

    // fork: GEMM1 (independent of graph preprocessing) on s2
    cudaEventRecord(ev_fork, 0);
    cudaStreamWaitEvent(s2, ev_fork, 0);
    k_gemm1<<<gblocks, 256, 0, s2>>>(x, W1, N);

    // preprocessing on the main stream
    k_count<<<qedge_blocks, 256>>>(ei, E, N);
    k_scan<<<NBLK, 1024>>>();
    cudaEventRecord(ev_scan, 0);

    // s2: premultiply gh by dis once both gemm1 (s2-ordered) and scan (event) are done
    cudaStreamWaitEvent(s2, ev_scan, 0);
    k_premult<<<(NPAD * 8 + 255) / 256, 256, 0, s2>>>();
    cudaEventRecord(ev_gemm, s2);

    // main: CSR fill
    k_fill<<<qedge_blocks, 256>>>(ei, E, N);

    // join, then fused layer-1 aggregation + layer-2 transform
    cudaStreamWaitEvent(0, ev_gemm, 0);
    k_gg2<<<gblocks, 256>>>(W2, b1);

    // fused layer-2 aggregation + layer-3 transform
    k_g2l3<<<(N * 8 + 255) / 256, 256>>>(W3, b2, b3, out, N);

    // layer-3 aggregation
    k_gather_out<<<(N + 255) / 256, 256>>>(out, N);
}